// round 15
// baseline (speedup 1.0000x reference)
#include <cuda_runtime.h>
#include <cuda_fp16.h>
#include <cstdint>
#include <cstddef>

#define NN 8192
#define INF 512
#define OF 64
#define SPLITJ 8
#define JCHUNK (NN / SPLITJ)
#define NKT (JCHUNK / 32)
#define SCALE 0.00390625f   // 2^-8, folded into e1/f1; cancels in num/den

// ---------------- device scratch ----------------
__device__ float g_WH[NN * OF];
__device__ float g_wh1[NN], g_wh2[NN];
__device__ float g_e1[NN], g_f1[NN], g_e2[NN], g_f2[NN];
__device__ uint2 g_Bf2[(NN / 32) * 16 * 32];         // fp16 B fragments, 1MB
__device__ float g_num[(size_t)SPLITJ * NN * OF];
__device__ float g_den[SPLITJ * NN];

// smem layout (dynamic): [0,8K) B 2 stages; [8K,40K) adj 2 stages; [40K,52K) params
#define SB_BYTES 8192
#define SADJ_BYTES 32768
#define SMEM_T (SB_BYTES + SADJ_BYTES + 12288)

// ---------------- helpers ----------------
__device__ __forceinline__ uint32_t pkhf(float x, float y) {
    __half2 h = __floats2half2_rn(x, y);
    return *(uint32_t*)&h;
}
__device__ __forceinline__ uint32_t pkbf(float lo, float hi) {
    uint32_t r;
    asm("cvt.rn.bf16x2.f32 %0, %1, %2;" : "=r"(r) : "f"(hi), "f"(lo));
    return r;
}
// fp16 hi/lo split of a pair
__device__ __forceinline__ void split2h(float x, float y, uint32_t& h, uint32_t& l) {
    __half2 hh = __floats2half2_rn(x, y);
    h = *(uint32_t*)&hh;
    float lx = x - __low2float(hh);
    float ly = y - __high2float(hh);
    l = pkhf(lx, ly);
}
__device__ __forceinline__ void wpair(int2 a, float rw, float re, float rf,
                                      float2 w2, float2 e2, float2 f2,
                                      uint32_t& h, uint32_t& l) {
    float s0 = rw + w2.x, s1 = rw + w2.y;
    float w0 = a.x ? ((s0 > 0.f) ? re * e2.x : rf * f2.x) : 0.f;
    float w1 = a.y ? ((s1 > 0.f) ? re * e2.y : rf * f2.y) : 0.f;
    split2h(w0, w1, h, l);
}
__device__ __forceinline__ void mma_f16(float* c, const uint32_t* a,
                                        uint32_t b0, uint32_t b1) {
    asm volatile(
        "mma.sync.aligned.m16n8k16.row.col.f32.f16.f16.f32 "
        "{%0,%1,%2,%3}, {%4,%5,%6,%7}, {%8,%9}, {%0,%1,%2,%3};"
        : "+f"(c[0]), "+f"(c[1]), "+f"(c[2]), "+f"(c[3])
        : "r"(a[0]), "r"(a[1]), "r"(a[2]), "r"(a[3]), "r"(b0), "r"(b1));
}
#define ONESH 0x3C003C00u
__device__ __forceinline__ uint32_t s2u(const void* p) {
    return (uint32_t)__cvta_generic_to_shared(p);
}
__device__ __forceinline__ void cpa8(uint32_t d, const void* s) {
    asm volatile("cp.async.ca.shared.global [%0], [%1], 8;" :: "r"(d), "l"(s));
}
__device__ __forceinline__ void cpa16(uint32_t d, const void* s) {
    asm volatile("cp.async.cg.shared.global [%0], [%1], 16;" :: "r"(d), "l"(s));
}
#define CP_COMMIT() asm volatile("cp.async.commit_group;" ::: "memory")
#define CP_WAIT1() asm volatile("cp.async.wait_group 1;" ::: "memory")

// ---------------- kernel 1: WH = h @ W (fp32 exact) ----------------
__global__ void gemm_wh(const float* __restrict__ h, const float* __restrict__ Wm) {
    __shared__ float hs[64][36];
    __shared__ float Ws[32][68];
    const int tid = threadIdx.x;
    const int ibase = blockIdx.x * 64;
    const int tx = tid & 15, ty = tid >> 4;
    const int r0 = ty * 4, c0 = tx * 4;
    float acc[4][4] = {};
    for (int kt = 0; kt < INF; kt += 32) {
        __syncthreads();
#pragma unroll
        for (int q = 0; q < 2; q++) {
            int idx = tid + q * 256;
            int row = idx >> 3, kq = idx & 7;
            *(float4*)&hs[row][kq * 4] = *(const float4*)&h[(size_t)(ibase + row) * INF + kt + kq * 4];
            int kr = idx >> 4, cq = idx & 15;
            *(float4*)&Ws[kr][cq * 4] = *(const float4*)&Wm[(size_t)(kt + kr) * OF + cq * 4];
        }
        __syncthreads();
#pragma unroll
        for (int k = 0; k < 32; k++) {
            float4 b = *(const float4*)&Ws[k][c0];
#pragma unroll
            for (int r = 0; r < 4; r++) {
                float av = hs[r0 + r][k];
                acc[r][0] += av * b.x; acc[r][1] += av * b.y;
                acc[r][2] += av * b.z; acc[r][3] += av * b.w;
            }
        }
    }
#pragma unroll
    for (int r = 0; r < 4; r++)
        *(float4*)&g_WH[(size_t)(ibase + r0 + r) * OF + c0] =
            make_float4(acc[r][0], acc[r][1], acc[r][2], acc[r][3]);
}

// ---------------- kernel 2: per-row stats (SCALE folded into e1/f1) ----------------
__global__ void row_stats(const float* __restrict__ a) {
    const int lane = threadIdx.x & 31;
    const int wid = threadIdx.x >> 5;
    const int row = blockIdx.x * 8 + wid;
    float v0 = g_WH[row * OF + lane];
    float v1 = g_WH[row * OF + 32 + lane];
    float p1 = v0 * a[lane] + v1 * a[lane + 32];
    float p2 = v0 * a[64 + lane] + v1 * a[96 + lane];
#pragma unroll
    for (int off = 16; off; off >>= 1) {
        p1 += __shfl_xor_sync(0xffffffffu, p1, off);
        p2 += __shfl_xor_sync(0xffffffffu, p2, off);
    }
    if (lane == 0) {
        g_wh1[row] = p1; g_wh2[row] = p2;
        g_e1[row] = expf(p1) * SCALE; g_f1[row] = expf(0.01f * p1) * SCALE;
        g_e2[row] = expf(p2); g_f2[row] = expf(0.01f * p2);
    }
}

// ---------------- kernel 2b: B (=WH) -> fp16 mma fragments ----------------
__global__ void wht_prep() {
    int t = blockIdx.x * 256 + threadIdx.x;        // 0 .. 131071
    int lane = t & 31;
    int n = (t >> 5) & 7;
    int s = (t >> 8) & 1;
    int c = t >> 9;
    int j0 = c * 32 + s * 16 + 2 * (lane & 3);
    int f = n * 8 + (lane >> 2);
    uint32_t b0 = pkhf(g_WH[(size_t)j0 * OF + f], g_WH[(size_t)(j0 + 1) * OF + f]);
    uint32_t b1 = pkhf(g_WH[(size_t)(j0 + 8) * OF + f], g_WH[(size_t)(j0 + 9) * OF + f]);
    g_Bf2[t] = make_uint2(b0, b1);
}

// ---------------- kernel 3: fused attention GEMM, 32 rows/warp, cp.async ----------------
__global__ void __launch_bounds__(128, 4) attn(const int* __restrict__ adj) {
    extern __shared__ __align__(16) unsigned char sm[];
    uint2* sB = (uint2*)sm;                          // [2][512]
    int2* sAdj = (int2*)(sm + SB_BYTES);             // [2][4 warps][16 slots][32 lanes]
    float* sW2 = (float*)(sm + SB_BYTES + SADJ_BYTES);
    float* sE2 = sW2 + JCHUNK;
    float* sF2 = sE2 + JCHUNK;

    const int tid = threadIdx.x;
    const int lane = tid & 31;
    const int warp = tid >> 5;
    const int ibase = blockIdx.x * 128;
    const int split = blockIdx.y;
    const int g = lane >> 2, qp = lane & 3;
    const int rg = ibase + warp * 32 + g;
    const int jbase = split * JCHUNK;

    // row params: 4 row-groups rg, rg+8, rg+16, rg+24
    float rw[4], re[4], rf[4];
#pragma unroll
    for (int r = 0; r < 4; r++) {
        rw[r] = g_wh1[rg + r * 8];
        re[r] = g_e1[rg + r * 8];
        rf[r] = g_f1[rg + r * 8];
    }

    // params -> smem (one time)
#pragma unroll
    for (int q = 0; q < 2; q++) {
        int i4 = (tid + q * 128) * 4;
        *(float4*)&sW2[i4] = *(const float4*)&g_wh2[jbase + i4];
        *(float4*)&sE2[i4] = *(const float4*)&g_e2[jbase + i4];
        *(float4*)&sF2[i4] = *(const float4*)&g_f2[jbase + i4];
    }

    // adjacency source pointers (4 row streams), lane-resolved
    const int* ap[4];
#pragma unroll
    for (int r = 0; r < 4; r++)
        ap[r] = adj + (size_t)(rg + r * 8) * NN + 2 * qp;

    const uint32_t adjb = s2u(sAdj) + (uint32_t)(warp * 512 + lane) * 8;
    const uint32_t bb = s2u(sB) + (uint32_t)tid * 16;

    // issue stage for tile 0
    {
        const int jc = jbase;
#pragma unroll
        for (int sl = 0; sl < 16; sl++)
            cpa8(adjb + (uint32_t)sl * 256, ap[sl >> 2] + jc + (sl & 3) * 8);
        const uint4* bsrc = (const uint4*)g_Bf2 + (size_t)(jc >> 5) * 256 + tid;
        cpa16(bb, bsrc);
        cpa16(bb + 2048, bsrc + 128);
    }
    CP_COMMIT();

    float acc[2][8][4];
    float den[2][4];
#pragma unroll
    for (int m = 0; m < 2; m++) {
#pragma unroll
        for (int n = 0; n < 8; n++)
#pragma unroll
            for (int q = 0; q < 4; q++) acc[m][n][q] = 0.f;
#pragma unroll
        for (int q = 0; q < 4; q++) den[m][q] = 0.f;
    }

    for (int t = 0; t < NKT; t++) {
        const int cb = t & 1;
        // issue stage for tile t+1
        if (t + 1 < NKT) {
            const int st = (t + 1) & 1;
            const int jc = jbase + (t + 1) * 32;
            const uint32_t ab = adjb + (uint32_t)st * 16384;
#pragma unroll
            for (int sl = 0; sl < 16; sl++)
                cpa8(ab + (uint32_t)sl * 256, ap[sl >> 2] + jc + (sl & 3) * 8);
            const uint4* bsrc = (const uint4*)g_Bf2 + (size_t)(jc >> 5) * 256 + tid;
            cpa16(bb + (uint32_t)st * 4096, bsrc);
            cpa16(bb + (uint32_t)st * 4096 + 2048, bsrc + 128);
        }
        CP_COMMIT();
        CP_WAIT1();
        __syncthreads();

        const uint2* bp = sB + cb * 512 + lane;
        const int2* adp = sAdj + cb * 2048 + warp * 512 + lane;

#pragma unroll
        for (int s = 0; s < 2; s++) {
            const int c0 = t * 32 + s * 16 + 2 * qp;
            float2 w2a = *(const float2*)&sW2[c0];
            float2 e2a = *(const float2*)&sE2[c0];
            float2 f2a = *(const float2*)&sF2[c0];
            float2 w2b = *(const float2*)&sW2[c0 + 8];
            float2 e2b = *(const float2*)&sE2[c0 + 8];
            float2 f2b = *(const float2*)&sF2[c0 + 8];

            // B fragments for this k-step
            uint2 B[8];
#pragma unroll
            for (int n = 0; n < 8; n++) B[n] = bp[(s * 8 + n) * 32];

#pragma unroll
            for (int m = 0; m < 2; m++) {
                int2 a00 = adp[((m * 2 + 0) * 4 + 2 * s) * 32];
                int2 a10 = adp[((m * 2 + 1) * 4 + 2 * s) * 32];
                int2 a01 = adp[((m * 2 + 0) * 4 + 2 * s + 1) * 32];
                int2 a11 = adp[((m * 2 + 1) * 4 + 2 * s + 1) * 32];
                uint32_t Ah[4], Al[4];
                wpair(a00, rw[2 * m], re[2 * m], rf[2 * m], w2a, e2a, f2a, Ah[0], Al[0]);
                wpair(a10, rw[2 * m + 1], re[2 * m + 1], rf[2 * m + 1], w2a, e2a, f2a, Ah[1], Al[1]);
                wpair(a01, rw[2 * m], re[2 * m], rf[2 * m], w2b, e2b, f2b, Ah[2], Al[2]);
                wpair(a11, rw[2 * m + 1], re[2 * m + 1], rf[2 * m + 1], w2b, e2b, f2b, Ah[3], Al[3]);
#pragma unroll
                for (int n = 0; n < 8; n++) mma_f16(acc[m][n], Ah, B[n].x, B[n].y);
                mma_f16(den[m], Ah, ONESH, ONESH);
#pragma unroll
                for (int n = 0; n < 8; n++) mma_f16(acc[m][n], Al, B[n].x, B[n].y);
                mma_f16(den[m], Al, ONESH, ONESH);
            }
        }
        __syncthreads();   // all warps done with stage cb before it is overwritten
    }

    // ---- epilogue ----
    if (qp == 0) {
#pragma unroll
        for (int m = 0; m < 2; m++) {
            g_den[split * NN + rg + 16 * m] = den[m][0];
            g_den[split * NN + rg + 16 * m + 8] = den[m][2];
        }
    }
#pragma unroll
    for (int m = 0; m < 2; m++)
#pragma unroll
        for (int n = 0; n < 8; n++) {
            size_t ba = ((size_t)split * NN + rg + 16 * m) * OF + n * 8 + qp * 2;
            *(float2*)&g_num[ba] = make_float2(acc[m][n][0], acc[m][n][1]);
            *(float2*)&g_num[ba + 8 * (size_t)OF] = make_float2(acc[m][n][2], acc[m][n][3]);
        }
}

// ---------------- kernel 4: reduce partials, divide, ELU ----------------
__global__ void finalize_k(float* __restrict__ out) {
    int idx = blockIdx.x * 256 + threadIdx.x;
    int i = idx >> 6, f = idx & 63;
    float num = 0.f, den = 0.f;
#pragma unroll
    for (int s = 0; s < SPLITJ; s++) {
        num += g_num[((size_t)s * NN + i) * OF + f];
        den += g_den[s * NN + i];
    }
    float x = num / den;
    out[idx] = (x > 0.f) ? x : expm1f(x);
}

// ---------------- launch ----------------
extern "C" void kernel_launch(void* const* d_in, const int* in_sizes, int n_in,
                              void* d_out, int out_size) {
    const float* h = nullptr; const int* adj = nullptr;
    const float* Wm = nullptr; const float* a = nullptr;
    for (int i = 0; i < n_in; i++) {
        switch (in_sizes[i]) {
            case NN * INF: h = (const float*)d_in[i]; break;
            case NN * NN:  adj = (const int*)d_in[i]; break;
            case INF * OF: Wm = (const float*)d_in[i]; break;
            case 2 * OF:   a = (const float*)d_in[i]; break;
            default: break;
        }
    }
    cudaFuncSetAttribute(attn, cudaFuncAttributeMaxDynamicSharedMemorySize, SMEM_T);
    gemm_wh<<<NN / 64, 256>>>(h, Wm);
    row_stats<<<NN / 8, 256>>>(a);
    wht_prep<<<512, 256>>>();
    dim3 g(NN / 128, SPLITJ);
    attn<<<g, 128, SMEM_T>>>(adj);
    finalize_k<<<(NN * OF) / 256, 256>>>((float*)d_out);
}